// round 8
// baseline (speedup 1.0000x reference)
#include <cuda_runtime.h>
#include <cuda_bf16.h>

// ---------------------------------------------------------------------------
// RticCompositionModule — collapsed computation.
// BN over the batch axis of a broadcast row == BN bias exactly, so all 32
// vmap slices are identical: compute ONE [32,4096] compose, broadcast x32.
//
// Round-5: tensor-core GEMM. W is streamed from DRAM in fp32 ONCE, split
// in-kernel into bf16 hi/lo (hi = truncation, lo = bf16(w-hi), exact sub),
// A pre-split into bf16 hi/lo planes by producers. Product:
//   A@W ≈ Ah@Wh + Ah@Wl + Al@Wh    (error ~2^-16, random sign)
// via mma.sync.m16n8k16.bf16 with fp32 accumulators. GEMM is DRAM-bound.
// ---------------------------------------------------------------------------

#define E_DIM 4096
#define H_DIM 2048
#define MROWS 32

typedef unsigned int uint;
typedef unsigned short ushort;

// ---- scratch (device globals; no allocation allowed) ----
__device__ ushort g_xh [MROWS * 2 * E_DIM];  // fused A hi (K=8192, [m][k])
__device__ ushort g_xl [MROWS * 2 * E_DIM];
__device__ ushort g_fh [MROWS * E_DIM];
__device__ ushort g_fl [MROWS * E_DIM];
__device__ ushort g_r1h[MROWS * E_DIM];
__device__ ushort g_r1l[MROWS * E_DIM];
__device__ ushort g_hh [MROWS * H_DIM];
__device__ ushort g_hl [MROWS * H_DIM];
__device__ ushort g_ffh[MROWS * E_DIM];
__device__ ushort g_ffl[MROWS * E_DIM];
__device__ float  g_part[1048576];           // split-K partials (<=4MB, L2)
__device__ float  g_f   [MROWS * E_DIM];
__device__ float  g_gate[MROWS * E_DIM];
__device__ float  g_ff  [MROWS * E_DIM];

#define SEL_X  0
#define SEL_F  1
#define SEL_R1 2
#define SEL_H  3
#define SEL_FF 4

// ---- helpers ----
__device__ __forceinline__ uint smem_u32(const void* p) {
    return (uint)__cvta_generic_to_shared(p);
}
__device__ __forceinline__ void cpasync16(uint dst, const void* src) {
    asm volatile("cp.async.ca.shared.global [%0], [%1], 16;" :: "r"(dst), "l"(src));
}
__device__ __forceinline__ float4 ldcs4(const float* p) {
    float4 v;
    asm("ld.global.cs.v4.f32 {%0,%1,%2,%3}, [%4];"
        : "=f"(v.x), "=f"(v.y), "=f"(v.z), "=f"(v.w) : "l"(p));
    return v;
}
// split two fp32 into packed bf16x2 hi (truncation) and lo (rn of remainder)
__device__ __forceinline__ void cvt_pair(float x, float y, uint& h, uint& l) {
    uint bx = __float_as_uint(x), by = __float_as_uint(y);
    asm("prmt.b32 %0, %1, %2, 0x7632;" : "=r"(h) : "r"(bx), "r"(by));
    float lx = x - __uint_as_float(bx & 0xffff0000u);
    float ly = y - __uint_as_float(by & 0xffff0000u);
    asm("cvt.rn.bf16x2.f32 %0, %1, %2;" : "=r"(l) : "f"(ly), "f"(lx));
}
__device__ __forceinline__ void split_scalar(float v, ushort& hb, ushort& lb) {
    uint b = __float_as_uint(v);
    hb = (ushort)(b >> 16);
    float lo = v - __uint_as_float(b & 0xffff0000u);
    __nv_bfloat16 x = __float2bfloat16(lo);
    lb = reinterpret_cast<ushort&>(x);
}
__device__ __forceinline__ void sts128(uint addr, uint a, uint b, uint c, uint d) {
    asm volatile("st.shared.v4.b32 [%0], {%1,%2,%3,%4};"
                 :: "r"(addr), "r"(a), "r"(b), "r"(c), "r"(d));
}
__device__ __forceinline__ void ldsm_x4(uint* r, uint addr) {
    asm volatile("ldmatrix.sync.aligned.m8n8.x4.shared.b16 {%0,%1,%2,%3}, [%4];"
                 : "=r"(r[0]), "=r"(r[1]), "=r"(r[2]), "=r"(r[3]) : "r"(addr));
}
__device__ __forceinline__ void ldsm_x2t(uint* r, uint addr) {
    asm volatile("ldmatrix.sync.aligned.m8n8.x2.trans.shared.b16 {%0,%1}, [%2];"
                 : "=r"(r[0]), "=r"(r[1]) : "r"(addr));
}
__device__ __forceinline__ void mma16816(float* c, const uint* a, const uint* b) {
    asm volatile(
        "mma.sync.aligned.m16n8k16.row.col.f32.bf16.bf16.f32 "
        "{%0,%1,%2,%3}, {%4,%5,%6,%7}, {%8,%9}, {%0,%1,%2,%3};"
        : "+f"(c[0]), "+f"(c[1]), "+f"(c[2]), "+f"(c[3])
        : "r"(a[0]), "r"(a[1]), "r"(a[2]), "r"(a[3]), "r"(b[0]), "r"(b[1]));
}

// ---------------------------------------------------------------------------
// pre: xi = relu(BN(image)) -> hi/lo planes of fused A (K=8192);
//      rows [4096+c] = relu(fs_bn_b[E+c]) for all m.
// ---------------------------------------------------------------------------
__global__ void pre_kernel(const float* __restrict__ img,
                           const float* __restrict__ bng,
                           const float* __restrict__ bnb) {
    int c = blockIdx.x * blockDim.x + threadIdx.x;   // 0..4095
    float v[MROWS];
    float s = 0.f;
#pragma unroll
    for (int m = 0; m < MROWS; ++m) { v[m] = img[m * E_DIM + c]; s += v[m]; }
    float mu = s * (1.f / 32.f);
    float s2 = 0.f;
#pragma unroll
    for (int m = 0; m < MROWS; ++m) { float d = v[m] - mu; s2 += d * d; }
    float rs = rsqrtf(s2 * (1.f / 32.f) + 1e-5f);
    float gg = bng[c], bb = bnb[c];
    ushort xth, xtl;
    split_scalar(fmaxf(bnb[E_DIM + c], 0.f), xth, xtl);
#pragma unroll
    for (int m = 0; m < MROWS; ++m) {
        float o = fmaxf((v[m] - mu) * rs * gg + bb, 0.f);
        ushort hb, lb; split_scalar(o, hb, lb);
        size_t i = (size_t)m * (2 * E_DIM) + c;
        g_xh[i] = hb; g_xl[i] = lb;
        g_xh[i + E_DIM] = xth; g_xl[i + E_DIM] = xtl;
    }
}

// ---------------------------------------------------------------------------
// Tensor-core GEMM: part[s][32][N] = A[32][k0:k0+kslice] @ W[k0:k0+kslice][N]
// Block 256 thr (8 warps). Block tile 32 x 128 (warp = 32 x 16).
// Per 32-k stage: W fp32 LDG (16KB/block) -> bf16 hi/lo cvt -> STS;
// A hi/lo via cp.async. ldmatrix + 24 mma per warp per stage.
// Smem rows padded (A 80B, W 272B) -> conflict-free ldmatrix.
// ---------------------------------------------------------------------------
#define ASTG (32 * 40 * 2)     // bytes per A plane-stage
#define WSTG (32 * 136 * 2)    // bytes per W plane-stage

__global__ void __launch_bounds__(256, 2)
gemm_tc(int aSel, const float* __restrict__ W, int N, int AK, int kslice) {
    const ushort* Ah = (aSel == SEL_X)  ? g_xh
                     : (aSel == SEL_F)  ? g_fh
                     : (aSel == SEL_R1) ? g_r1h
                     : (aSel == SEL_H)  ? g_hh
                                        : g_ffh;
    const ushort* Al = (aSel == SEL_X)  ? g_xl
                     : (aSel == SEL_F)  ? g_fl
                     : (aSel == SEL_R1) ? g_r1l
                     : (aSel == SEL_H)  ? g_hl
                                        : g_ffl;
    __shared__ __align__(16) ushort sW[2 * 2 * 32 * 136];  // [stage][plane]
    __shared__ __align__(16) ushort sA[2 * 2 * 32 * 40];

    const int tid  = threadIdx.x;
    const int lane = tid & 31;
    const int warp = tid >> 5;
    const int bn0  = blockIdx.x * 128;
    const int k0   = blockIdx.y * kslice;
    const int warpN = warp * 16;
    const uint sAb = smem_u32(sA);
    const uint sWb = smem_u32(sW);

    // lane constants for ldmatrix addressing
    const int rowA  = ((lane >> 3) & 1) * 8 + (lane & 7);
    const int colA8 = (lane >> 4) * 8;
    const int l16   = lane & 15;
    const int rowB  = ((l16 >> 3) * 8) + (l16 & 7);

    // A staging role
    const int aPlane = tid >> 7;           // 0: hi, 1: lo
    const int aRow   = (tid >> 2) & 31;
    const int aChunk = tid & 3;
    const ushort* Ap = aPlane ? Al : Ah;

    // W staging role
    const int wk = tid >> 3;               // k row 0..31
    const int wn = (tid & 7) * 16;         // 16 n per thread

    float acc[2][2][4];
#pragma unroll
    for (int a = 0; a < 2; ++a)
#pragma unroll
        for (int b = 0; b < 2; ++b)
#pragma unroll
            for (int q = 0; q < 4; ++q) acc[a][b][q] = 0.f;

    const int nt = kslice / 32;
    float4 wv[4];

    // ---- prologue: stage 0 ----
    {
        const float* ws = W + (size_t)(k0 + wk) * N + bn0 + wn;
        wv[0] = ldcs4(ws); wv[1] = ldcs4(ws + 4);
        wv[2] = ldcs4(ws + 8); wv[3] = ldcs4(ws + 12);
        cpasync16(sAb + aPlane * ASTG + aRow * 80 + aChunk * 16,
                  Ap + (size_t)aRow * AK + k0 + aChunk * 8);
        asm volatile("cp.async.commit_group;");
        uint h[8], l[8];
#pragma unroll
        for (int p = 0; p < 4; ++p) {
            cvt_pair(wv[p].x, wv[p].y, h[2 * p], l[2 * p]);
            cvt_pair(wv[p].z, wv[p].w, h[2 * p + 1], l[2 * p + 1]);
        }
        uint dh = sWb + wk * 272 + wn * 2;
        sts128(dh, h[0], h[1], h[2], h[3]);
        sts128(dh + 16, h[4], h[5], h[6], h[7]);
        uint dl = dh + WSTG;
        sts128(dl, l[0], l[1], l[2], l[3]);
        sts128(dl + 16, l[4], l[5], l[6], l[7]);
        asm volatile("cp.async.wait_group 0;");
        __syncthreads();
    }

    for (int t = 0; t < nt; ++t) {
        const int c = t & 1;
        const int n = c ^ 1;
        const bool more = (t + 1 < nt);
        if (more) {
            const int kt = k0 + (t + 1) * 32;
            const float* ws = W + (size_t)(kt + wk) * N + bn0 + wn;
            wv[0] = ldcs4(ws); wv[1] = ldcs4(ws + 4);
            wv[2] = ldcs4(ws + 8); wv[3] = ldcs4(ws + 12);
            cpasync16(sAb + (n * 2 + aPlane) * ASTG + aRow * 80 + aChunk * 16,
                      Ap + (size_t)aRow * AK + kt + aChunk * 8);
        }
        asm volatile("cp.async.commit_group;");

        // ---- compute on buffer c ----
        const uint aH = sAb + (c * 2) * ASTG;
        const uint aL = aH + ASTG;
        const uint wH = sWb + (c * 2) * WSTG;
        const uint wL = wH + WSTG;
#pragma unroll
        for (int ko = 0; ko < 32; ko += 16) {
            uint ah[2][4], al[2][4];
#pragma unroll
            for (int mt = 0; mt < 2; ++mt) {
                uint off = (mt * 16 + rowA) * 80 + (ko + colA8) * 2;
                ldsm_x4(ah[mt], aH + off);
                ldsm_x4(al[mt], aL + off);
            }
#pragma unroll
            for (int nt2 = 0; nt2 < 2; ++nt2) {
                uint bh[2], bl[2];
                uint boff = (ko + rowB) * 272 + (warpN + nt2 * 8) * 2;
                ldsm_x2t(bh, wH + boff);
                ldsm_x2t(bl, wL + boff);
#pragma unroll
                for (int mt = 0; mt < 2; ++mt) {
                    mma16816(acc[mt][nt2], ah[mt], bh);
                    mma16816(acc[mt][nt2], ah[mt], bl);
                    mma16816(acc[mt][nt2], al[mt], bh);
                }
            }
        }

        if (more) {
            uint h[8], l[8];
#pragma unroll
            for (int p = 0; p < 4; ++p) {
                cvt_pair(wv[p].x, wv[p].y, h[2 * p], l[2 * p]);
                cvt_pair(wv[p].z, wv[p].w, h[2 * p + 1], l[2 * p + 1]);
            }
            uint dh = sWb + (n * 2) * WSTG + wk * 272 + wn * 2;
            sts128(dh, h[0], h[1], h[2], h[3]);
            sts128(dh + 16, h[4], h[5], h[6], h[7]);
            uint dl = dh + WSTG;
            sts128(dl, l[0], l[1], l[2], l[3]);
            sts128(dl + 16, l[4], l[5], l[6], l[7]);
        }
        asm volatile("cp.async.wait_group 0;");
        __syncthreads();
    }

    // ---- store partials ----
    float* pbase = g_part + (size_t)blockIdx.y * MROWS * N + bn0;
    const int prow = lane >> 2;
    const int pcol = (lane & 3) * 2;
#pragma unroll
    for (int mt = 0; mt < 2; ++mt)
#pragma unroll
        for (int nt2 = 0; nt2 < 2; ++nt2) {
            int r = mt * 16 + prow;
            int cc = warpN + nt2 * 8 + pcol;
            *reinterpret_cast<float2*>(&pbase[(size_t)r * N + cc]) =
                make_float2(acc[mt][nt2][0], acc[mt][nt2][1]);
            *reinterpret_cast<float2*>(&pbase[(size_t)(r + 8) * N + cc]) =
                make_float2(acc[mt][nt2][2], acc[mt][nt2][3]);
        }
}

// ---------------------------------------------------------------------------
// Elementwise reducers (one thread per element, 512x256). K layout [m][4096].
// mode 0: bias          -> g_f  + f planes
// mode 1: bias, sigmoid -> g_gate
// mode 2: bias + g_f    -> g_ff + ff planes
// mode 3: bias + g_ff   -> g_ff + ff planes
// ---------------------------------------------------------------------------
__global__ void reduce_elem(const float* __restrict__ bias, int ksp, int mode) {
    int idx = blockIdx.x * 256 + threadIdx.x;    // 32*4096
    int c = idx & (E_DIM - 1);
    float v = bias[c];
#pragma unroll 4
    for (int sl = 0; sl < ksp; ++sl)
        v += g_part[(size_t)sl * (MROWS * E_DIM) + idx];
    if (mode == 0) {
        g_f[idx] = v;
        split_scalar(v, g_fh[idx], g_fl[idx]);
    } else if (mode == 1) {
        g_gate[idx] = 1.f / (1.f + expf(-v));
    } else {
        v += (mode == 2) ? g_f[idx] : g_ff[idx];
        g_ff[idx] = v;
        split_scalar(v, g_ffh[idx], g_ffl[idx]);
    }
}

// ---------------------------------------------------------------------------
// Fused split-K reduce + BN + ReLU -> bf16 hi/lo planes. 256 thr, 32 cols.
// outSel: 0 -> r1 planes (N=E), 1 -> h planes (N=H)
// ---------------------------------------------------------------------------
__global__ void reduce_bn_relu(const float* __restrict__ bias,
                               const float* __restrict__ gam,
                               const float* __restrict__ bet,
                               int N, int ksp, int outSel) {
    __shared__ float ssum[MROWS][33];
    __shared__ float smu[MROWS], srs[MROWS];
    int c  = threadIdx.x & 31;
    int mg = threadIdx.x >> 5;
    int gc = blockIdx.x * 32 + c;
    float b = bias[gc];
#pragma unroll
    for (int r = 0; r < 4; ++r) {
        int m = mg * 4 + r;
        float s = b;
        const float* p = g_part + (size_t)m * N + gc;
#pragma unroll 4
        for (int sl = 0; sl < ksp; ++sl)
            s += p[(size_t)sl * MROWS * N];
        ssum[m][c] = s;
    }
    __syncthreads();
    if (threadIdx.x < 32) {
        int cc = threadIdx.x;
        float su = 0.f;
#pragma unroll
        for (int m = 0; m < MROWS; ++m) su += ssum[m][cc];
        float mu = su * (1.f / 32.f);
        float s2 = 0.f;
#pragma unroll
        for (int m = 0; m < MROWS; ++m) { float d = ssum[m][cc] - mu; s2 += d * d; }
        smu[cc] = mu;
        srs[cc] = rsqrtf(s2 * (1.f / 32.f) + 1e-5f);
    }
    __syncthreads();
    float gg = gam[gc], bb = bet[gc];
    ushort* oh = outSel ? g_hh : g_r1h;
    ushort* ol = outSel ? g_hl : g_r1l;
#pragma unroll
    for (int r = 0; r < 4; ++r) {
        int m = mg * 4 + r;
        float o = fmaxf((ssum[m][c] - smu[c]) * srs[c] * gg + bb, 0.f);
        split_scalar(o, oh[(size_t)m * N + gc], ol[(size_t)m * N + gc]);
    }
}

// ---------------------------------------------------------------------------
// final: R = img*g + ff*(1-g); broadcast 32x along the text axis (float4)
// ---------------------------------------------------------------------------
__global__ void final_kernel(const float* __restrict__ img, float* __restrict__ out) {
    int q = blockIdx.x * 256 + threadIdx.x;   // 32768 float4 groups
    float4 gv = *reinterpret_cast<const float4*>(&g_gate[q * 4]);
    float4 fv = *reinterpret_cast<const float4*>(&g_ff[q * 4]);
    float4 iv = *reinterpret_cast<const float4*>(&img[q * 4]);
    float4 r;
    r.x = iv.x * gv.x + fv.x * (1.f - gv.x);
    r.y = iv.y * gv.y + fv.y * (1.f - gv.y);
    r.z = iv.z * gv.z + fv.z * (1.f - gv.z);
    r.w = iv.w * gv.w + fv.w * (1.f - gv.w);
    float4* o4 = reinterpret_cast<float4*>(out);
#pragma unroll
    for (int j = 0; j < 32; ++j)
        o4[(size_t)j * 32768 + q] = r;
}

// ---------------------------------------------------------------------------
extern "C" void kernel_launch(void* const* d_in, const int* in_sizes, int n_in,
                              void* d_out, int out_size) {
    const float* img     = (const float*)d_in[0];
    // d_in[1] = text_features: provably unused (BN of broadcast row == bias)
    const float* fs_bn_g = (const float*)d_in[2];
    const float* fs_bn_b = (const float*)d_in[3];
    const float* fs_w    = (const float*)d_in[4];
    const float* fs_b    = (const float*)d_in[5];
    const float* gt_w1   = (const float*)d_in[6];
    const float* gt_b1   = (const float*)d_in[7];
    const float* gt_bn_g = (const float*)d_in[8];
    const float* gt_bn_b = (const float*)d_in[9];
    const float* gt_w2   = (const float*)d_in[10];
    const float* gt_b2   = (const float*)d_in[11];
    const float* ee_w1   = (const float*)d_in[12];
    const float* ee_b1   = (const float*)d_in[13];
    const float* ee_bn_g = (const float*)d_in[14];
    const float* ee_bn_b = (const float*)d_in[15];
    const float* ee_w2   = (const float*)d_in[16];
    const float* ee_b2   = (const float*)d_in[17];
    float* out = (float*)d_out;

    // 0) image BN + relu -> fused bf16 hi/lo A (K=8192)
    pre_kernel<<<16, 256>>>(img, fs_bn_g, fs_bn_b);

    // 1) fusion: f = [xi ; xt] @ fs_w + fs_b   (K=8192)
    gemm_tc<<<dim3(32, 8), 256>>>(SEL_X, fs_w, E_DIM, 2 * E_DIM, 1024);
    reduce_elem<<<512, 256>>>(fs_b, 8, 0);

    // 2) gating
    gemm_tc<<<dim3(32, 4), 256>>>(SEL_F, gt_w1, E_DIM, E_DIM, 1024);
    reduce_bn_relu<<<128, 256>>>(gt_b1, gt_bn_g, gt_bn_b, E_DIM, 4, 0);
    gemm_tc<<<dim3(32, 4), 256>>>(SEL_R1, gt_w2, E_DIM, E_DIM, 1024);
    reduce_elem<<<512, 256>>>(gt_b2, 4, 1);

    // 3) three error-encoding residual blocks
    for (int i = 0; i < 3; ++i) {
        gemm_tc<<<dim3(16, 8), 256>>>((i == 0) ? SEL_F : SEL_FF,
                                      ee_w1 + (size_t)i * E_DIM * H_DIM,
                                      H_DIM, E_DIM, 512);
        reduce_bn_relu<<<64, 256>>>(ee_b1 + i * H_DIM, ee_bn_g + i * H_DIM,
                                    ee_bn_b + i * H_DIM, H_DIM, 8, 1);
        gemm_tc<<<dim3(32, 4), 256>>>(SEL_H, ee_w2 + (size_t)i * H_DIM * E_DIM,
                                      E_DIM, H_DIM, 512);
        reduce_elem<<<512, 256>>>(ee_b2 + i * E_DIM, 4, (i == 0) ? 2 : 3);
    }

    // 4) gate-combine and broadcast to [32, 32, 4096]
    final_kernel<<<128, 256>>>(img, out);

    (void)in_sizes; (void)n_in; (void)out_size;
}

// round 9
// speedup vs baseline: 1.0085x; 1.0085x over previous
#include <cuda_runtime.h>
#include <cuda_bf16.h>

// ---------------------------------------------------------------------------
// RticCompositionModule — collapsed computation.
// BN over the batch axis of a broadcast row == BN bias exactly, so all 32
// vmap slices are identical: compute ONE [32,4096] compose, broadcast x32.
//
// Round-5: tensor-core GEMM. W is streamed from DRAM in fp32 ONCE, split
// in-kernel into bf16 hi/lo (hi = truncation, lo = bf16(w-hi), exact sub),
// A pre-split into bf16 hi/lo planes by producers. Product:
//   A@W ≈ Ah@Wh + Ah@Wl + Al@Wh    (error ~2^-16, random sign)
// via mma.sync.m16n8k16.bf16 with fp32 accumulators. GEMM is DRAM-bound.
// ---------------------------------------------------------------------------

#define E_DIM 4096
#define H_DIM 2048
#define MROWS 32

typedef unsigned int uint;
typedef unsigned short ushort;

// ---- scratch (device globals; no allocation allowed) ----
__device__ ushort g_xh [MROWS * 2 * E_DIM];  // fused A hi (K=8192, [m][k])
__device__ ushort g_xl [MROWS * 2 * E_DIM];
__device__ ushort g_fh [MROWS * E_DIM];
__device__ ushort g_fl [MROWS * E_DIM];
__device__ ushort g_r1h[MROWS * E_DIM];
__device__ ushort g_r1l[MROWS * E_DIM];
__device__ ushort g_hh [MROWS * H_DIM];
__device__ ushort g_hl [MROWS * H_DIM];
__device__ ushort g_ffh[MROWS * E_DIM];
__device__ ushort g_ffl[MROWS * E_DIM];
__device__ float  g_part[1048576];           // split-K partials (<=4MB, L2)
__device__ float  g_f   [MROWS * E_DIM];
__device__ float  g_gate[MROWS * E_DIM];
__device__ float  g_ff  [MROWS * E_DIM];

#define SEL_X  0
#define SEL_F  1
#define SEL_R1 2
#define SEL_H  3
#define SEL_FF 4

// ---- helpers ----
__device__ __forceinline__ uint smem_u32(const void* p) {
    return (uint)__cvta_generic_to_shared(p);
}
__device__ __forceinline__ void cpasync16(uint dst, const void* src) {
    asm volatile("cp.async.ca.shared.global [%0], [%1], 16;" :: "r"(dst), "l"(src));
}
__device__ __forceinline__ float4 ldcs4(const float* p) {
    float4 v;
    asm("ld.global.cs.v4.f32 {%0,%1,%2,%3}, [%4];"
        : "=f"(v.x), "=f"(v.y), "=f"(v.z), "=f"(v.w) : "l"(p));
    return v;
}
// split two fp32 into packed bf16x2 hi (truncation) and lo (rn of remainder)
__device__ __forceinline__ void cvt_pair(float x, float y, uint& h, uint& l) {
    uint bx = __float_as_uint(x), by = __float_as_uint(y);
    asm("prmt.b32 %0, %1, %2, 0x7632;" : "=r"(h) : "r"(bx), "r"(by));
    float lx = x - __uint_as_float(bx & 0xffff0000u);
    float ly = y - __uint_as_float(by & 0xffff0000u);
    asm("cvt.rn.bf16x2.f32 %0, %1, %2;" : "=r"(l) : "f"(ly), "f"(lx));
}
__device__ __forceinline__ void split_scalar(float v, ushort& hb, ushort& lb) {
    uint b = __float_as_uint(v);
    hb = (ushort)(b >> 16);
    float lo = v - __uint_as_float(b & 0xffff0000u);
    __nv_bfloat16 x = __float2bfloat16(lo);
    lb = reinterpret_cast<ushort&>(x);
}
__device__ __forceinline__ void sts128(uint addr, uint a, uint b, uint c, uint d) {
    asm volatile("st.shared.v4.b32 [%0], {%1,%2,%3,%4};"
                 :: "r"(addr), "r"(a), "r"(b), "r"(c), "r"(d));
}
__device__ __forceinline__ void ldsm_x4(uint* r, uint addr) {
    asm volatile("ldmatrix.sync.aligned.m8n8.x4.shared.b16 {%0,%1,%2,%3}, [%4];"
                 : "=r"(r[0]), "=r"(r[1]), "=r"(r[2]), "=r"(r[3]) : "r"(addr));
}
__device__ __forceinline__ void ldsm_x2t(uint* r, uint addr) {
    asm volatile("ldmatrix.sync.aligned.m8n8.x2.trans.shared.b16 {%0,%1}, [%2];"
                 : "=r"(r[0]), "=r"(r[1]) : "r"(addr));
}
__device__ __forceinline__ void mma16816(float* c, const uint* a, const uint* b) {
    asm volatile(
        "mma.sync.aligned.m16n8k16.row.col.f32.bf16.bf16.f32 "
        "{%0,%1,%2,%3}, {%4,%5,%6,%7}, {%8,%9}, {%0,%1,%2,%3};"
        : "+f"(c[0]), "+f"(c[1]), "+f"(c[2]), "+f"(c[3])
        : "r"(a[0]), "r"(a[1]), "r"(a[2]), "r"(a[3]), "r"(b[0]), "r"(b[1]));
}

// ---------------------------------------------------------------------------
// pre: xi = relu(BN(image)) -> hi/lo planes of fused A (K=8192);
//      rows [4096+c] = relu(fs_bn_b[E+c]) for all m.
// ---------------------------------------------------------------------------
__global__ void pre_kernel(const float* __restrict__ img,
                           const float* __restrict__ bng,
                           const float* __restrict__ bnb) {
    int c = blockIdx.x * blockDim.x + threadIdx.x;   // 0..4095
    float v[MROWS];
    float s = 0.f;
#pragma unroll
    for (int m = 0; m < MROWS; ++m) { v[m] = img[m * E_DIM + c]; s += v[m]; }
    float mu = s * (1.f / 32.f);
    float s2 = 0.f;
#pragma unroll
    for (int m = 0; m < MROWS; ++m) { float d = v[m] - mu; s2 += d * d; }
    float rs = rsqrtf(s2 * (1.f / 32.f) + 1e-5f);
    float gg = bng[c], bb = bnb[c];
    ushort xth, xtl;
    split_scalar(fmaxf(bnb[E_DIM + c], 0.f), xth, xtl);
#pragma unroll
    for (int m = 0; m < MROWS; ++m) {
        float o = fmaxf((v[m] - mu) * rs * gg + bb, 0.f);
        ushort hb, lb; split_scalar(o, hb, lb);
        size_t i = (size_t)m * (2 * E_DIM) + c;
        g_xh[i] = hb; g_xl[i] = lb;
        g_xh[i + E_DIM] = xth; g_xl[i + E_DIM] = xtl;
    }
}

// ---------------------------------------------------------------------------
// Tensor-core GEMM: part[s][32][N] = A[32][k0:k0+kslice] @ W[k0:k0+kslice][N]
// Block 256 thr (8 warps). Block tile 32 x 128 (warp = 32 x 16).
// Per 32-k stage: W fp32 LDG (16KB/block) -> bf16 hi/lo cvt -> STS;
// A hi/lo via cp.async. ldmatrix + 24 mma per warp per stage.
// Smem rows padded (A 80B, W 272B) -> conflict-free ldmatrix.
// ---------------------------------------------------------------------------
#define ASTG (32 * 40 * 2)     // bytes per A plane-stage
#define WSTG (32 * 136 * 2)    // bytes per W plane-stage

__global__ void __launch_bounds__(256, 2)
gemm_tc(int aSel, const float* __restrict__ W, int N, int AK, int kslice) {
    const ushort* Ah = (aSel == SEL_X)  ? g_xh
                     : (aSel == SEL_F)  ? g_fh
                     : (aSel == SEL_R1) ? g_r1h
                     : (aSel == SEL_H)  ? g_hh
                                        : g_ffh;
    const ushort* Al = (aSel == SEL_X)  ? g_xl
                     : (aSel == SEL_F)  ? g_fl
                     : (aSel == SEL_R1) ? g_r1l
                     : (aSel == SEL_H)  ? g_hl
                                        : g_ffl;
    __shared__ __align__(16) ushort sW[2 * 2 * 32 * 136];  // [stage][plane]
    __shared__ __align__(16) ushort sA[2 * 2 * 32 * 40];

    const int tid  = threadIdx.x;
    const int lane = tid & 31;
    const int warp = tid >> 5;
    const int bn0  = blockIdx.x * 128;
    const int k0   = blockIdx.y * kslice;
    const int warpN = warp * 16;
    const uint sAb = smem_u32(sA);
    const uint sWb = smem_u32(sW);

    // lane constants for ldmatrix addressing
    const int rowA  = ((lane >> 3) & 1) * 8 + (lane & 7);
    const int colA8 = (lane >> 4) * 8;
    const int l16   = lane & 15;
    const int rowB  = ((l16 >> 3) * 8) + (l16 & 7);

    // A staging role
    const int aPlane = tid >> 7;           // 0: hi, 1: lo
    const int aRow   = (tid >> 2) & 31;
    const int aChunk = tid & 3;
    const ushort* Ap = aPlane ? Al : Ah;

    // W staging role
    const int wk = tid >> 3;               // k row 0..31
    const int wn = (tid & 7) * 16;         // 16 n per thread

    float acc[2][2][4];
#pragma unroll
    for (int a = 0; a < 2; ++a)
#pragma unroll
        for (int b = 0; b < 2; ++b)
#pragma unroll
            for (int q = 0; q < 4; ++q) acc[a][b][q] = 0.f;

    const int nt = kslice / 32;
    float4 wv[4];

    // ---- prologue: stage 0 ----
    {
        const float* ws = W + (size_t)(k0 + wk) * N + bn0 + wn;
        wv[0] = ldcs4(ws); wv[1] = ldcs4(ws + 4);
        wv[2] = ldcs4(ws + 8); wv[3] = ldcs4(ws + 12);
        cpasync16(sAb + aPlane * ASTG + aRow * 80 + aChunk * 16,
                  Ap + (size_t)aRow * AK + k0 + aChunk * 8);
        asm volatile("cp.async.commit_group;");
        uint h[8], l[8];
#pragma unroll
        for (int p = 0; p < 4; ++p) {
            cvt_pair(wv[p].x, wv[p].y, h[2 * p], l[2 * p]);
            cvt_pair(wv[p].z, wv[p].w, h[2 * p + 1], l[2 * p + 1]);
        }
        uint dh = sWb + wk * 272 + wn * 2;
        sts128(dh, h[0], h[1], h[2], h[3]);
        sts128(dh + 16, h[4], h[5], h[6], h[7]);
        uint dl = dh + WSTG;
        sts128(dl, l[0], l[1], l[2], l[3]);
        sts128(dl + 16, l[4], l[5], l[6], l[7]);
        asm volatile("cp.async.wait_group 0;");
        __syncthreads();
    }

    for (int t = 0; t < nt; ++t) {
        const int c = t & 1;
        const int n = c ^ 1;
        const bool more = (t + 1 < nt);
        if (more) {
            const int kt = k0 + (t + 1) * 32;
            const float* ws = W + (size_t)(kt + wk) * N + bn0 + wn;
            wv[0] = ldcs4(ws); wv[1] = ldcs4(ws + 4);
            wv[2] = ldcs4(ws + 8); wv[3] = ldcs4(ws + 12);
            cpasync16(sAb + (n * 2 + aPlane) * ASTG + aRow * 80 + aChunk * 16,
                      Ap + (size_t)aRow * AK + kt + aChunk * 8);
        }
        asm volatile("cp.async.commit_group;");

        // ---- compute on buffer c ----
        const uint aH = sAb + (c * 2) * ASTG;
        const uint aL = aH + ASTG;
        const uint wH = sWb + (c * 2) * WSTG;
        const uint wL = wH + WSTG;
#pragma unroll
        for (int ko = 0; ko < 32; ko += 16) {
            uint ah[2][4], al[2][4];
#pragma unroll
            for (int mt = 0; mt < 2; ++mt) {
                uint off = (mt * 16 + rowA) * 80 + (ko + colA8) * 2;
                ldsm_x4(ah[mt], aH + off);
                ldsm_x4(al[mt], aL + off);
            }
#pragma unroll
            for (int nt2 = 0; nt2 < 2; ++nt2) {
                uint bh[2], bl[2];
                uint boff = (ko + rowB) * 272 + (warpN + nt2 * 8) * 2;
                ldsm_x2t(bh, wH + boff);
                ldsm_x2t(bl, wL + boff);
#pragma unroll
                for (int mt = 0; mt < 2; ++mt) {
                    mma16816(acc[mt][nt2], ah[mt], bh);
                    mma16816(acc[mt][nt2], ah[mt], bl);
                    mma16816(acc[mt][nt2], al[mt], bh);
                }
            }
        }

        if (more) {
            uint h[8], l[8];
#pragma unroll
            for (int p = 0; p < 4; ++p) {
                cvt_pair(wv[p].x, wv[p].y, h[2 * p], l[2 * p]);
                cvt_pair(wv[p].z, wv[p].w, h[2 * p + 1], l[2 * p + 1]);
            }
            uint dh = sWb + (n * 2) * WSTG + wk * 272 + wn * 2;
            sts128(dh, h[0], h[1], h[2], h[3]);
            sts128(dh + 16, h[4], h[5], h[6], h[7]);
            uint dl = dh + WSTG;
            sts128(dl, l[0], l[1], l[2], l[3]);
            sts128(dl + 16, l[4], l[5], l[6], l[7]);
        }
        asm volatile("cp.async.wait_group 0;");
        __syncthreads();
    }

    // ---- store partials ----
    float* pbase = g_part + (size_t)blockIdx.y * MROWS * N + bn0;
    const int prow = lane >> 2;
    const int pcol = (lane & 3) * 2;
#pragma unroll
    for (int mt = 0; mt < 2; ++mt)
#pragma unroll
        for (int nt2 = 0; nt2 < 2; ++nt2) {
            int r = mt * 16 + prow;
            int cc = warpN + nt2 * 8 + pcol;
            *reinterpret_cast<float2*>(&pbase[(size_t)r * N + cc]) =
                make_float2(acc[mt][nt2][0], acc[mt][nt2][1]);
            *reinterpret_cast<float2*>(&pbase[(size_t)(r + 8) * N + cc]) =
                make_float2(acc[mt][nt2][2], acc[mt][nt2][3]);
        }
}

// ---------------------------------------------------------------------------
// Elementwise reducers (one thread per element, 512x256). K layout [m][4096].
// mode 0: bias          -> g_f  + f planes
// mode 1: bias, sigmoid -> g_gate
// mode 2: bias + g_f    -> g_ff + ff planes
// mode 3: bias + g_ff   -> g_ff + ff planes
// ---------------------------------------------------------------------------
__global__ void reduce_elem(const float* __restrict__ bias, int ksp, int mode) {
    int idx = blockIdx.x * 256 + threadIdx.x;    // 32*4096
    int c = idx & (E_DIM - 1);
    float v = bias[c];
#pragma unroll 4
    for (int sl = 0; sl < ksp; ++sl)
        v += g_part[(size_t)sl * (MROWS * E_DIM) + idx];
    if (mode == 0) {
        g_f[idx] = v;
        split_scalar(v, g_fh[idx], g_fl[idx]);
    } else if (mode == 1) {
        g_gate[idx] = 1.f / (1.f + expf(-v));
    } else {
        v += (mode == 2) ? g_f[idx] : g_ff[idx];
        g_ff[idx] = v;
        split_scalar(v, g_ffh[idx], g_ffl[idx]);
    }
}

// ---------------------------------------------------------------------------
// Fused split-K reduce + BN + ReLU -> bf16 hi/lo planes. 256 thr, 32 cols.
// outSel: 0 -> r1 planes (N=E), 1 -> h planes (N=H)
// ---------------------------------------------------------------------------
__global__ void reduce_bn_relu(const float* __restrict__ bias,
                               const float* __restrict__ gam,
                               const float* __restrict__ bet,
                               int N, int ksp, int outSel) {
    __shared__ float ssum[MROWS][33];
    __shared__ float smu[MROWS], srs[MROWS];
    int c  = threadIdx.x & 31;
    int mg = threadIdx.x >> 5;
    int gc = blockIdx.x * 32 + c;
    float b = bias[gc];
#pragma unroll
    for (int r = 0; r < 4; ++r) {
        int m = mg * 4 + r;
        float s = b;
        const float* p = g_part + (size_t)m * N + gc;
#pragma unroll 4
        for (int sl = 0; sl < ksp; ++sl)
            s += p[(size_t)sl * MROWS * N];
        ssum[m][c] = s;
    }
    __syncthreads();
    if (threadIdx.x < 32) {
        int cc = threadIdx.x;
        float su = 0.f;
#pragma unroll
        for (int m = 0; m < MROWS; ++m) su += ssum[m][cc];
        float mu = su * (1.f / 32.f);
        float s2 = 0.f;
#pragma unroll
        for (int m = 0; m < MROWS; ++m) { float d = ssum[m][cc] - mu; s2 += d * d; }
        smu[cc] = mu;
        srs[cc] = rsqrtf(s2 * (1.f / 32.f) + 1e-5f);
    }
    __syncthreads();
    float gg = gam[gc], bb = bet[gc];
    ushort* oh = outSel ? g_hh : g_r1h;
    ushort* ol = outSel ? g_hl : g_r1l;
#pragma unroll
    for (int r = 0; r < 4; ++r) {
        int m = mg * 4 + r;
        float o = fmaxf((ssum[m][c] - smu[c]) * srs[c] * gg + bb, 0.f);
        split_scalar(o, oh[(size_t)m * N + gc], ol[(size_t)m * N + gc]);
    }
}

// ---------------------------------------------------------------------------
// final: R = img*g + ff*(1-g); broadcast 32x along the text axis (float4)
// ---------------------------------------------------------------------------
__global__ void final_kernel(const float* __restrict__ img, float* __restrict__ out) {
    int q = blockIdx.x * 256 + threadIdx.x;   // 32768 float4 groups
    float4 gv = *reinterpret_cast<const float4*>(&g_gate[q * 4]);
    float4 fv = *reinterpret_cast<const float4*>(&g_ff[q * 4]);
    float4 iv = *reinterpret_cast<const float4*>(&img[q * 4]);
    float4 r;
    r.x = iv.x * gv.x + fv.x * (1.f - gv.x);
    r.y = iv.y * gv.y + fv.y * (1.f - gv.y);
    r.z = iv.z * gv.z + fv.z * (1.f - gv.z);
    r.w = iv.w * gv.w + fv.w * (1.f - gv.w);
    float4* o4 = reinterpret_cast<float4*>(out);
#pragma unroll
    for (int j = 0; j < 32; ++j)
        o4[(size_t)j * 32768 + q] = r;
}

// ---------------------------------------------------------------------------
extern "C" void kernel_launch(void* const* d_in, const int* in_sizes, int n_in,
                              void* d_out, int out_size) {
    const float* img     = (const float*)d_in[0];
    // d_in[1] = text_features: provably unused (BN of broadcast row == bias)
    const float* fs_bn_g = (const float*)d_in[2];
    const float* fs_bn_b = (const float*)d_in[3];
    const float* fs_w    = (const float*)d_in[4];
    const float* fs_b    = (const float*)d_in[5];
    const float* gt_w1   = (const float*)d_in[6];
    const float* gt_b1   = (const float*)d_in[7];
    const float* gt_bn_g = (const float*)d_in[8];
    const float* gt_bn_b = (const float*)d_in[9];
    const float* gt_w2   = (const float*)d_in[10];
    const float* gt_b2   = (const float*)d_in[11];
    const float* ee_w1   = (const float*)d_in[12];
    const float* ee_b1   = (const float*)d_in[13];
    const float* ee_bn_g = (const float*)d_in[14];
    const float* ee_bn_b = (const float*)d_in[15];
    const float* ee_w2   = (const float*)d_in[16];
    const float* ee_b2   = (const float*)d_in[17];
    float* out = (float*)d_out;

    // 0) image BN + relu -> fused bf16 hi/lo A (K=8192)
    pre_kernel<<<16, 256>>>(img, fs_bn_g, fs_bn_b);

    // 1) fusion: f = [xi ; xt] @ fs_w + fs_b   (K=8192)
    gemm_tc<<<dim3(32, 8), 256>>>(SEL_X, fs_w, E_DIM, 2 * E_DIM, 1024);
    reduce_elem<<<512, 256>>>(fs_b, 8, 0);

    // 2) gating
    gemm_tc<<<dim3(32, 4), 256>>>(SEL_F, gt_w1, E_DIM, E_DIM, 1024);
    reduce_bn_relu<<<128, 256>>>(gt_b1, gt_bn_g, gt_bn_b, E_DIM, 4, 0);
    gemm_tc<<<dim3(32, 4), 256>>>(SEL_R1, gt_w2, E_DIM, E_DIM, 1024);
    reduce_elem<<<512, 256>>>(gt_b2, 4, 1);

    // 3) three error-encoding residual blocks
    for (int i = 0; i < 3; ++i) {
        gemm_tc<<<dim3(16, 8), 256>>>((i == 0) ? SEL_F : SEL_FF,
                                      ee_w1 + (size_t)i * E_DIM * H_DIM,
                                      H_DIM, E_DIM, 512);
        reduce_bn_relu<<<64, 256>>>(ee_b1 + i * H_DIM, ee_bn_g + i * H_DIM,
                                    ee_bn_b + i * H_DIM, H_DIM, 8, 1);
        gemm_tc<<<dim3(32, 4), 256>>>(SEL_H, ee_w2 + (size_t)i * H_DIM * E_DIM,
                                      E_DIM, H_DIM, 512);
        reduce_elem<<<512, 256>>>(ee_b2 + i * E_DIM, 4, (i == 0) ? 2 : 3);
    }

    // 4) gate-combine and broadcast to [32, 32, 4096]
    final_kernel<<<128, 256>>>(img, out);

    (void)in_sizes; (void)n_in; (void)out_size;
}